// round 1
// baseline (speedup 1.0000x reference)
#include <cuda_runtime.h>
#include <cuda_bf16.h>

#define D 128
#define ALPHA 0.1f
#define BETA 0.22314355131420976f  /* log(1.25) */
#define MAXN 50000

__device__ float g_agg[MAXN * D];
__device__ float g_deg[MAXN];
__device__ float g_norm[MAXN];

__global__ void zero_kernel(int n) {
    int tid = blockIdx.x * blockDim.x + threadIdx.x;
    int stride = gridDim.x * blockDim.x;
    int total4 = n * D / 4;
    float4 z = make_float4(0.f, 0.f, 0.f, 0.f);
    for (int i = tid; i < total4; i += stride)
        reinterpret_cast<float4*>(g_agg)[i] = z;
    for (int i = tid; i < n; i += stride)
        g_deg[i] = 0.f;
}

__global__ void deg_kernel(const int* __restrict__ dst, int ne) {
    int e = blockIdx.x * blockDim.x + threadIdx.x;
    if (e < ne) atomicAdd(&g_deg[dst[e]], 1.0f);
}

__global__ void norm_kernel(int n) {
    int i = blockIdx.x * blockDim.x + threadIdx.x;
    if (i < n) g_norm[i] = rsqrtf(fmaxf(g_deg[i], 1.0f));
}

// One warp per edge: lane l moves 4 floats (float4) of the 128-wide row.
// agg[dst] += feat[src] * norm[src]  via red.global.add.v4.f32 (no return).
__global__ void scatter_kernel(const float* __restrict__ feat,
                               const int* __restrict__ src,
                               const int* __restrict__ dst, int ne) {
    int gw = (blockIdx.x * blockDim.x + threadIdx.x) >> 5;
    int lane = threadIdx.x & 31;
    if (gw >= ne) return;
    int s = src[gw];
    int d = dst[gw];
    float nm = g_norm[s];
    float4 v = reinterpret_cast<const float4*>(feat + (size_t)s * D)[lane];
    float4 r = make_float4(v.x * nm, v.y * nm, v.z * nm, v.w * nm);
    float* p = g_agg + (size_t)d * D + lane * 4;
    asm volatile("red.global.add.v4.f32 [%0], {%1, %2, %3, %4};"
                 :: "l"(p), "f"(r.x), "f"(r.y), "f"(r.z), "f"(r.w)
                 : "memory");
}

// Fused: h2 = agg*norm*(1-ALPHA) + feat_0*ALPHA (built into smem tile load)
//        out = (1-BETA)*h2 + BETA*(h2 @ W) + bias
// Block: 128 threads (thread = output column c), ROWS=16 rows per block.
#define ROWS 16
__global__ __launch_bounds__(128) void gemm_kernel(const float* __restrict__ feat0,
                                                   const float* __restrict__ W,
                                                   const float* __restrict__ bias,
                                                   float* __restrict__ out, int n) {
    __shared__ float sh[ROWS][D];
    const int c = threadIdx.x;
    const int r0 = blockIdx.x * ROWS;

    #pragma unroll
    for (int r = 0; r < ROWS; r++) {
        int row = r0 + r;
        float h2 = 0.f;
        if (row < n) {
            float nm = g_norm[row];
            h2 = g_agg[(size_t)row * D + c] * nm * (1.0f - ALPHA)
               + feat0[(size_t)row * D + c] * ALPHA;
        }
        sh[r][c] = h2;
    }
    __syncthreads();

    float acc[ROWS];
    #pragma unroll
    for (int r = 0; r < ROWS; r++) acc[r] = 0.f;

    for (int k = 0; k < D; k++) {
        float w = __ldg(&W[k * D + c]);   // coalesced, L1-resident (64KB total)
        #pragma unroll
        for (int r = 0; r < ROWS; r++)
            acc[r] = fmaf(sh[r][k], w, acc[r]);  // smem broadcast read
    }

    float b = bias[c];
    #pragma unroll
    for (int r = 0; r < ROWS; r++) {
        int row = r0 + r;
        if (row < n)
            out[(size_t)row * D + c] = (1.0f - BETA) * sh[r][c] + BETA * acc[r] + b;
    }
}

extern "C" void kernel_launch(void* const* d_in, const int* in_sizes, int n_in,
                              void* d_out, int out_size) {
    const float* feat  = (const float*)d_in[0];
    const float* feat0 = (const float*)d_in[1];
    const float* W     = (const float*)d_in[2];
    const float* bias  = (const float*)d_in[3];
    const int*   src   = (const int*)d_in[4];
    const int*   dst   = (const int*)d_in[5];
    float* out = (float*)d_out;

    int n  = in_sizes[0] / D;
    int ne = in_sizes[4];

    zero_kernel<<<512, 256>>>(n);
    deg_kernel<<<(ne + 255) / 256, 256>>>(dst, ne);
    norm_kernel<<<(n + 255) / 256, 256>>>(n);

    long long threads = (long long)ne * 32;
    int blocks = (int)((threads + 255) / 256);
    scatter_kernel<<<blocks, 256>>>(feat, src, dst, ne);

    gemm_kernel<<<(n + ROWS - 1) / ROWS, 128>>>(feat0, W, bias, out, n);
}

// round 2
// speedup vs baseline: 1.2575x; 1.2575x over previous
#include <cuda_runtime.h>
#include <cuda_bf16.h>

#define D 128
#define ALPHA 0.1f
#define BETA 0.22314355131420976f        /* log(1.25) */
#define ONE_MB 0.7768564486857909f       /* 1 - BETA */
#define MAXN 50000
#define MAXE 600000
#define SCAN_B 256

__device__ int   g_deg[MAXN];
__device__ int   g_off[MAXN + 1];
__device__ int   g_cursor[MAXN];
__device__ int   g_csrc[MAXE];
__device__ float g_norm[MAXN];
__device__ int   g_bsum[SCAN_B];
__device__ int   g_bscan[SCAN_B];

__global__ void zero_deg_kernel(int n) {
    int i = blockIdx.x * blockDim.x + threadIdx.x;
    if (i < n) g_deg[i] = 0;
}

__global__ void deg_kernel(const int* __restrict__ dst, int ne) {
    int e = blockIdx.x * blockDim.x + threadIdx.x;
    if (e < ne) atomicAdd(&g_deg[dst[e]], 1);
}

__global__ void norm_kernel(int n) {
    int i = blockIdx.x * blockDim.x + threadIdx.x;
    if (i < n) g_norm[i] = rsqrtf(fmaxf((float)g_deg[i], 1.0f));
}

// ---- 3-kernel exclusive scan over g_deg -> g_off ----
__global__ void scan_block_kernel(int n) {
    __shared__ int s[SCAN_B];
    int i = blockIdx.x * SCAN_B + threadIdx.x;
    int v = (i < n) ? g_deg[i] : 0;
    s[threadIdx.x] = v;
    __syncthreads();
    // Hillis-Steele inclusive scan
    #pragma unroll
    for (int off = 1; off < SCAN_B; off <<= 1) {
        int t = (threadIdx.x >= off) ? s[threadIdx.x - off] : 0;
        __syncthreads();
        s[threadIdx.x] += t;
        __syncthreads();
    }
    if (i < n) g_off[i] = s[threadIdx.x] - v;   // exclusive (local)
    if (threadIdx.x == SCAN_B - 1) g_bsum[blockIdx.x] = s[SCAN_B - 1];
}

__global__ void scan_top_kernel(int nb) {
    __shared__ int s[SCAN_B];
    int v = (threadIdx.x < nb) ? g_bsum[threadIdx.x] : 0;
    s[threadIdx.x] = v;
    __syncthreads();
    #pragma unroll
    for (int off = 1; off < SCAN_B; off <<= 1) {
        int t = (threadIdx.x >= off) ? s[threadIdx.x - off] : 0;
        __syncthreads();
        s[threadIdx.x] += t;
        __syncthreads();
    }
    if (threadIdx.x < nb) g_bscan[threadIdx.x] = s[threadIdx.x] - v; // exclusive
}

__global__ void scan_finish_kernel(int n, int ne) {
    int i = blockIdx.x * blockDim.x + threadIdx.x;
    if (i < n) {
        int o = g_off[i] + g_bscan[blockIdx.x * blockDim.x / SCAN_B + (threadIdx.x / SCAN_B)];
        // blockDim == SCAN_B so block index maps 1:1
        o = g_off[i] + g_bscan[blockIdx.x];
        g_off[i] = o;
        g_cursor[i] = o;
    }
    if (i == 0) g_off[n] = ne;
}

__global__ void permute_kernel(const int* __restrict__ src,
                               const int* __restrict__ dst, int ne) {
    int e = blockIdx.x * blockDim.x + threadIdx.x;
    if (e < ne) {
        int d = dst[e];
        int pos = atomicAdd(&g_cursor[d], 1);
        g_csrc[pos] = src[e];
    }
}

// ---- fused: CSR gather-aggregate (16 rows) -> smem tile -> GEMM epilogue ----
// 128 threads = 4 warps. Warp w aggregates rows 4w..4w+3; lane owns 4 columns.
// Then thread c computes output column c for all 16 rows.
#define ROWS 16
__global__ __launch_bounds__(128) void fused_kernel(const float* __restrict__ feat,
                                                    const float* __restrict__ feat0,
                                                    const float* __restrict__ W,
                                                    const float* __restrict__ bias,
                                                    float* __restrict__ out, int n) {
    __shared__ float sh[ROWS][D];
    const int c    = threadIdx.x;
    const int warp = threadIdx.x >> 5;
    const int lane = threadIdx.x & 31;
    const int r0   = blockIdx.x * ROWS;

    // ---- aggregation phase ----
    #pragma unroll
    for (int rr = 0; rr < 4; rr++) {
        int row = r0 + warp * 4 + rr;
        float4 acc = make_float4(0.f, 0.f, 0.f, 0.f);
        if (row < n) {
            int beg = g_off[row];
            int end = g_off[row + 1];
            for (int j = beg; j < end; j++) {
                int s = g_csrc[j];              // broadcast LDG
                float nm = g_norm[s];           // broadcast LDG
                float4 v = __ldg((const float4*)(feat + (size_t)s * D) + lane);
                acc.x = fmaf(v.x, nm, acc.x);
                acc.y = fmaf(v.y, nm, acc.y);
                acc.z = fmaf(v.z, nm, acc.z);
                acc.w = fmaf(v.w, nm, acc.w);
            }
            float nmd = g_norm[row] * (1.0f - ALPHA);
            float4 f0 = __ldg((const float4*)(feat0 + (size_t)row * D) + lane);
            acc.x = acc.x * nmd + f0.x * ALPHA;
            acc.y = acc.y * nmd + f0.y * ALPHA;
            acc.z = acc.z * nmd + f0.z * ALPHA;
            acc.w = acc.w * nmd + f0.w * ALPHA;
        }
        *(float4*)&sh[warp * 4 + rr][lane * 4] = acc;
    }
    __syncthreads();

    // ---- GEMM phase: acc[r] = sum_k sh[r][k] * W[k][c] ----
    float acc[ROWS];
    #pragma unroll
    for (int r = 0; r < ROWS; r++) acc[r] = 0.f;

    for (int k = 0; k < D; k += 4) {
        float w0 = __ldg(&W[(k + 0) * D + c]);
        float w1 = __ldg(&W[(k + 1) * D + c]);
        float w2 = __ldg(&W[(k + 2) * D + c]);
        float w3 = __ldg(&W[(k + 3) * D + c]);
        #pragma unroll
        for (int r = 0; r < ROWS; r++) {
            float4 h4 = *(const float4*)&sh[r][k];   // broadcast LDS.128
            acc[r] = fmaf(h4.x, w0, acc[r]);
            acc[r] = fmaf(h4.y, w1, acc[r]);
            acc[r] = fmaf(h4.z, w2, acc[r]);
            acc[r] = fmaf(h4.w, w3, acc[r]);
        }
    }

    float b = bias[c];
    #pragma unroll
    for (int r = 0; r < ROWS; r++) {
        int row = r0 + r;
        if (row < n)
            out[(size_t)row * D + c] = ONE_MB * sh[r][c] + BETA * acc[r] + b;
    }
}

extern "C" void kernel_launch(void* const* d_in, const int* in_sizes, int n_in,
                              void* d_out, int out_size) {
    const float* feat  = (const float*)d_in[0];
    const float* feat0 = (const float*)d_in[1];
    const float* W     = (const float*)d_in[2];
    const float* bias  = (const float*)d_in[3];
    const int*   src   = (const int*)d_in[4];
    const int*   dst   = (const int*)d_in[5];
    float* out = (float*)d_out;

    int n  = in_sizes[0] / D;
    int ne = in_sizes[4];
    int nb = (n + SCAN_B - 1) / SCAN_B;      // 196 for n=50000

    zero_deg_kernel<<<(n + 255) / 256, 256>>>(n);
    deg_kernel<<<(ne + 255) / 256, 256>>>(dst, ne);
    norm_kernel<<<(n + 255) / 256, 256>>>(n);
    scan_block_kernel<<<nb, SCAN_B>>>(n);
    scan_top_kernel<<<1, SCAN_B>>>(nb);
    scan_finish_kernel<<<nb, SCAN_B>>>(n, ne);
    permute_kernel<<<(ne + 255) / 256, 256>>>(src, dst, ne);
    fused_kernel<<<(n + ROWS - 1) / ROWS, 128>>>(feat, feat0, W, bias, out, n);
}

// round 4
// speedup vs baseline: 1.3875x; 1.1034x over previous
#include <cuda_runtime.h>
#include <cuda_bf16.h>

#define D 128
#define ALPHA 0.1f
#define BETA 0.22314355131420976f        /* log(1.25) */
#define ONE_MB 0.7768564486857909f       /* 1 - BETA */
#define MAXN 50000
#define MAXE 600000
#define SCAN_B 256

__device__ int   g_deg[MAXN];
__device__ int   g_off[MAXN + 1];
__device__ int   g_cursor[MAXN];
__device__ int   g_csrc[MAXE];
__device__ float g_norm[MAXN];
__device__ float g_h[MAXN * D];
__device__ int   g_bsum[SCAN_B];
__device__ int   g_bscan[SCAN_B];

#define FMA_F32X2(d, a, b, c) \
    asm("fma.rn.f32x2 %0, %1, %2, %3;" : "=l"(d) : "l"(a), "l"(b), "l"(c))
#define PACK_F32X2(out, lo, hi) \
    asm("mov.b64 %0, {%1, %2};" : "=l"(out) : "f"(lo), "f"(hi))
#define UNPACK_F32X2(lo, hi, in) \
    asm("mov.b64 {%0, %1}, %2;" : "=f"(lo), "=f"(hi) : "l"(in))

__global__ void zero_deg_kernel(int n) {
    int i = blockIdx.x * blockDim.x + threadIdx.x;
    if (i < n) g_deg[i] = 0;
}

__global__ void deg_kernel(const int* __restrict__ dst, int ne) {
    int e = blockIdx.x * blockDim.x + threadIdx.x;
    if (e < ne) atomicAdd(&g_deg[dst[e]], 1);
}

// block scan + norm computation fused
__global__ void scan_block_kernel(int n) {
    __shared__ int s[SCAN_B];
    int i = blockIdx.x * SCAN_B + threadIdx.x;
    int v = (i < n) ? g_deg[i] : 0;
    s[threadIdx.x] = v;
    __syncthreads();
    #pragma unroll
    for (int off = 1; off < SCAN_B; off <<= 1) {
        int t = (threadIdx.x >= off) ? s[threadIdx.x - off] : 0;
        __syncthreads();
        s[threadIdx.x] += t;
        __syncthreads();
    }
    if (i < n) {
        g_off[i] = s[threadIdx.x] - v;   // exclusive (local)
        g_norm[i] = rsqrtf(fmaxf((float)v, 1.0f));
    }
    if (threadIdx.x == SCAN_B - 1) g_bsum[blockIdx.x] = s[SCAN_B - 1];
}

__global__ void scan_top_kernel(int nb) {
    __shared__ int s[SCAN_B];
    int v = (threadIdx.x < nb) ? g_bsum[threadIdx.x] : 0;
    s[threadIdx.x] = v;
    __syncthreads();
    #pragma unroll
    for (int off = 1; off < SCAN_B; off <<= 1) {
        int t = (threadIdx.x >= off) ? s[threadIdx.x - off] : 0;
        __syncthreads();
        s[threadIdx.x] += t;
        __syncthreads();
    }
    if (threadIdx.x < nb) g_bscan[threadIdx.x] = s[threadIdx.x] - v;
}

__global__ void scan_finish_kernel(int n, int ne) {
    int i = blockIdx.x * blockDim.x + threadIdx.x;
    if (i < n) {
        int o = g_off[i] + g_bscan[blockIdx.x];
        g_off[i] = o;
        g_cursor[i] = o;
    }
    if (i == 0) g_off[n] = ne;
}

__global__ void permute_kernel(const int* __restrict__ src,
                               const int* __restrict__ dst, int ne) {
    int e = blockIdx.x * blockDim.x + threadIdx.x;
    if (e < ne) {
        int d = dst[e];
        int pos = atomicAdd(&g_cursor[d], 1);
        g_csrc[pos] = src[e];
    }
}

// ---- aggregation: one warp per destination row ----
// Chunk-load up to 32 edge indices + their norms coalesced, then broadcast via
// shuffle so each feat-row gather (LDG.128/lane) is independent -> high MLP.
__global__ __launch_bounds__(256) void agg_kernel(const float* __restrict__ feat,
                                                  const float* __restrict__ feat0,
                                                  int n) {
    int w    = (blockIdx.x * blockDim.x + threadIdx.x) >> 5;
    int lane = threadIdx.x & 31;
    if (w >= n) return;
    int beg = g_off[w];
    int end = g_off[w + 1];

    float4 acc = make_float4(0.f, 0.f, 0.f, 0.f);
    for (int j0 = beg; j0 < end; j0 += 32) {
        int jj = j0 + lane;
        int s = 0;
        float nmv = 0.f;
        if (jj < end) {
            s = g_csrc[jj];
            nmv = g_norm[s];
        }
        int m = min(32, end - j0);
        for (int e = 0; e < m; e++) {
            int   ss = __shfl_sync(0xffffffffu, s, e);
            float nm = __shfl_sync(0xffffffffu, nmv, e);
            float4 v = __ldg((const float4*)feat + (size_t)ss * 32 + lane);
            acc.x = fmaf(v.x, nm, acc.x);
            acc.y = fmaf(v.y, nm, acc.y);
            acc.z = fmaf(v.z, nm, acc.z);
            acc.w = fmaf(v.w, nm, acc.w);
        }
    }
    float nmd = g_norm[w] * (1.0f - ALPHA);
    float4 f0 = __ldg((const float4*)feat0 + (size_t)w * 32 + lane);
    float4 h;
    h.x = acc.x * nmd + f0.x * ALPHA;
    h.y = acc.y * nmd + f0.y * ALPHA;
    h.z = acc.z * nmd + f0.z * ALPHA;
    h.w = acc.w * nmd + f0.w * ALPHA;
    ((float4*)g_h)[(size_t)w * 32 + lane] = h;
}

// ---- GEMM with packed f32x2 FMA (pairs over adjacent k) ----
// thread = output column c; ROWS rows per block; h pairs come directly from
// broadcast LDS.128 (no packing movs); W pairs are register pairs.
// acc2 holds (sum over even k, sum over odd k); horizontal add at the end.
#define ROWS 16
__global__ __launch_bounds__(128) void gemm_kernel(const float* __restrict__ W,
                                                   const float* __restrict__ bias,
                                                   float* __restrict__ out, int n) {
    __shared__ float sh[ROWS][D];
    const int c  = threadIdx.x;
    const int r0 = blockIdx.x * ROWS;

    #pragma unroll
    for (int r = 0; r < ROWS; r++) {
        int row = r0 + r;
        sh[r][c] = (row < n) ? g_h[(size_t)row * D + c] : 0.f;
    }
    __syncthreads();

    unsigned long long acc2[ROWS];
    #pragma unroll
    for (int r = 0; r < ROWS; r++) acc2[r] = 0ULL;   // (0.f, 0.f)

    #pragma unroll 4
    for (int k = 0; k < D; k += 4) {
        float w0 = __ldg(&W[(k + 0) * D + c]);
        float w1 = __ldg(&W[(k + 1) * D + c]);
        float w2 = __ldg(&W[(k + 2) * D + c]);
        float w3 = __ldg(&W[(k + 3) * D + c]);
        unsigned long long wp01, wp23;
        PACK_F32X2(wp01, w0, w1);
        PACK_F32X2(wp23, w2, w3);
        #pragma unroll
        for (int r = 0; r < ROWS; r++) {
            ulonglong2 hp = *(const ulonglong2*)&sh[r][k];  // broadcast LDS.128
            FMA_F32X2(acc2[r], hp.x, wp01, acc2[r]);
            FMA_F32X2(acc2[r], hp.y, wp23, acc2[r]);
        }
    }

    float b = bias[c];
    #pragma unroll
    for (int r = 0; r < ROWS; r++) {
        int row = r0 + r;
        if (row < n) {
            float lo, hi;
            UNPACK_F32X2(lo, hi, acc2[r]);
            out[(size_t)row * D + c] = ONE_MB * sh[r][c] + BETA * (lo + hi) + b;
        }
    }
}

extern "C" void kernel_launch(void* const* d_in, const int* in_sizes, int n_in,
                              void* d_out, int out_size) {
    const float* feat  = (const float*)d_in[0];
    const float* feat0 = (const float*)d_in[1];
    const float* W     = (const float*)d_in[2];
    const float* bias  = (const float*)d_in[3];
    const int*   src   = (const int*)d_in[4];
    const int*   dst   = (const int*)d_in[5];
    float* out = (float*)d_out;

    int n  = in_sizes[0] / D;
    int ne = in_sizes[4];
    int nb = (n + SCAN_B - 1) / SCAN_B;      // 196 for n=50000

    zero_deg_kernel<<<(n + 255) / 256, 256>>>(n);
    deg_kernel<<<(ne + 255) / 256, 256>>>(dst, ne);
    scan_block_kernel<<<nb, SCAN_B>>>(n);
    scan_top_kernel<<<1, SCAN_B>>>(nb);
    scan_finish_kernel<<<nb, SCAN_B>>>(n, ne);
    permute_kernel<<<(ne + 255) / 256, 256>>>(src, dst, ne);

    int nwarps_blocks = (n * 32 + 255) / 256;   // one warp per row
    agg_kernel<<<nwarps_blocks, 256>>>(feat, feat0, n);

    gemm_kernel<<<(n + ROWS - 1) / ROWS, 128>>>(W, bias, out, n);
}

// round 5
// speedup vs baseline: 1.7249x; 1.2432x over previous
#include <cuda_runtime.h>
#include <cuda_bf16.h>

#define D 128
#define ALPHA 0.1f
#define BETA 0.22314355131420976f        /* log(1.25) */
#define ONE_MB 0.7768564486857909f       /* 1 - BETA */
#define MAXN 50000
#define MAXE 600000
#define SCAN_B 256

__device__ int   g_deg[MAXN];            // zero-initialized at load; re-zeroed each call
__device__ int   g_off[MAXN + 1];
__device__ int   g_cursor[MAXN];
__device__ int   g_csrc[MAXE];
__device__ float g_norm[MAXN];
__device__ float g_h[MAXN * D];
__device__ int   g_bsum[SCAN_B];
__device__ uint2 g_wperm[16 * 16 * 32];  // W in tf32 B-fragment order, 64KB

__device__ __forceinline__ unsigned f2tf32(float f) {
    unsigned r;
    asm("cvt.rna.tf32.f32 %0, %1;" : "=r"(r) : "f"(f));
    return r;
}

__global__ void deg_kernel(const int* __restrict__ dst, int ne) {
    int e = blockIdx.x * blockDim.x + threadIdx.x;
    if (e < ne) atomicAdd(&g_deg[dst[e]], 1);
}

// block-local exclusive scan + norm
__global__ void scan_block_kernel(int n) {
    __shared__ int s[SCAN_B];
    int i = blockIdx.x * SCAN_B + threadIdx.x;
    int v = (i < n) ? g_deg[i] : 0;
    s[threadIdx.x] = v;
    __syncthreads();
    #pragma unroll
    for (int off = 1; off < SCAN_B; off <<= 1) {
        int t = (threadIdx.x >= off) ? s[threadIdx.x - off] : 0;
        __syncthreads();
        s[threadIdx.x] += t;
        __syncthreads();
    }
    if (i < n) {
        g_off[i]  = s[threadIdx.x] - v;
        g_norm[i] = rsqrtf(fmaxf((float)v, 1.0f));
    }
    if (threadIdx.x == SCAN_B - 1) g_bsum[blockIdx.x] = s[SCAN_B - 1];
}

// each block reduce-sums bsum[0..bid-1] itself (no scan_top kernel)
__global__ void scan_finish_kernel(int n, int ne) {
    __shared__ int wsum[8];
    int t = threadIdx.x;
    int v = (t < blockIdx.x) ? g_bsum[t] : 0;
    #pragma unroll
    for (int o = 16; o > 0; o >>= 1) v += __shfl_down_sync(0xffffffffu, v, o);
    if ((t & 31) == 0) wsum[t >> 5] = v;
    __syncthreads();
    int prefix = wsum[0] + wsum[1] + wsum[2] + wsum[3]
               + wsum[4] + wsum[5] + wsum[6] + wsum[7];
    int i = blockIdx.x * blockDim.x + t;
    if (i < n) {
        int o = g_off[i] + prefix;
        g_off[i] = o;
        g_cursor[i] = o;
    }
    if (i == 0) g_off[n] = ne;
}

// permute edges into by-dst CSR; also re-zero g_deg for the next graph replay
__global__ void permute_kernel(const int* __restrict__ src,
                               const int* __restrict__ dst, int ne, int n) {
    int e = blockIdx.x * blockDim.x + threadIdx.x;
    if (e < ne) {
        int d = dst[e];
        int pos = atomicAdd(&g_cursor[d], 1);
        g_csrc[pos] = src[e];
        if (e < n) g_deg[e] = 0;
    }
}

// W[k][n] -> tf32 B-fragments for mma.m16n8k8 (b0=W[k0+l%4][n0+l/4], b1=+4 rows)
__global__ void wconv_kernel(const float* __restrict__ W) {
    int tid = blockIdx.x * blockDim.x + threadIdx.x;
    if (tid >= 16 * 16 * 32) return;
    int lane = tid & 31, tile = tid >> 5;
    int nt = tile & 15, kt = tile >> 4;
    int k = kt * 8 + (lane & 3);
    int nn = nt * 8 + (lane >> 2);
    uint2 b;
    b.x = f2tf32(W[k * D + nn]);
    b.y = f2tf32(W[(k + 4) * D + nn]);
    g_wperm[tile * 32 + lane] = b;
}

// ---- aggregation: one warp per destination row (unchanged, at L2 floor) ----
__global__ __launch_bounds__(256) void agg_kernel(const float* __restrict__ feat,
                                                  const float* __restrict__ feat0,
                                                  int n) {
    int w    = (blockIdx.x * blockDim.x + threadIdx.x) >> 5;
    int lane = threadIdx.x & 31;
    if (w >= n) return;
    int beg = g_off[w];
    int end = g_off[w + 1];

    float4 acc = make_float4(0.f, 0.f, 0.f, 0.f);
    for (int j0 = beg; j0 < end; j0 += 32) {
        int jj = j0 + lane;
        int s = 0;
        float nmv = 0.f;
        if (jj < end) {
            s = g_csrc[jj];
            nmv = g_norm[s];
        }
        int m = min(32, end - j0);
        for (int e = 0; e < m; e++) {
            int   ss = __shfl_sync(0xffffffffu, s, e);
            float nm = __shfl_sync(0xffffffffu, nmv, e);
            float4 v = __ldg((const float4*)feat + (size_t)ss * 32 + lane);
            acc.x = fmaf(v.x, nm, acc.x);
            acc.y = fmaf(v.y, nm, acc.y);
            acc.z = fmaf(v.z, nm, acc.z);
            acc.w = fmaf(v.w, nm, acc.w);
        }
    }
    float nmd = g_norm[w] * (1.0f - ALPHA);
    float4 f0 = __ldg((const float4*)feat0 + (size_t)w * 32 + lane);
    float4 h;
    h.x = acc.x * nmd + f0.x * ALPHA;
    h.y = acc.y * nmd + f0.y * ALPHA;
    h.z = acc.z * nmd + f0.z * ALPHA;
    h.w = acc.w * nmd + f0.w * ALPHA;
    ((float4*)g_h)[(size_t)w * 32 + lane] = h;
}

// ---- tensor-core GEMM: mma.sync.m16n8k8 tf32, fp32 accumulate ----
// Block = 128 threads (4 warps), 64 rows. Warp w owns rows w*16..w*16+15.
// smem keeps EXACT fp32 h (for the (1-beta)*h bypass); tf32 cvt at A-frag load.
#define GROWS 64
#define SH_PAD 132   /* 132 mod 32 = 4 -> conflict-free A-frag LDS */
__global__ __launch_bounds__(128) void mma_kernel(const float* __restrict__ bias,
                                                  float* __restrict__ out, int n) {
    __shared__ float sh[GROWS][SH_PAD];
    const int tid  = threadIdx.x;
    const int w    = tid >> 5;
    const int lane = tid & 31;
    const int r0   = blockIdx.x * GROWS;

    // stage 64x128 h tile (fp32): thread -> row tid/2, half tid&1
    {
        int r = tid >> 1, half = tid & 1;
        int row = r0 + r;
        const float4* srcp = (const float4*)(g_h + (size_t)row * D) + half * 16;
        #pragma unroll
        for (int i = 0; i < 16; i++) {
            float4 v = (row < n) ? __ldg(srcp + i) : make_float4(0.f, 0.f, 0.f, 0.f);
            *(float4*)&sh[r][half * 64 + i * 4] = v;
        }
    }
    __syncthreads();

    float acc[16][4];
    #pragma unroll
    for (int nt = 0; nt < 16; nt++)
        #pragma unroll
        for (int i = 0; i < 4; i++) acc[nt][i] = 0.f;

    const int ra = w * 16 + (lane >> 2);
    const int ca = lane & 3;

    #pragma unroll
    for (int kt = 0; kt < 16; kt++) {
        unsigned a0 = f2tf32(sh[ra][kt * 8 + ca]);
        unsigned a1 = f2tf32(sh[ra + 8][kt * 8 + ca]);
        unsigned a2 = f2tf32(sh[ra][kt * 8 + ca + 4]);
        unsigned a3 = f2tf32(sh[ra + 8][kt * 8 + ca + 4]);
        const uint2* bp = g_wperm + (kt * 16) * 32 + lane;
        #pragma unroll
        for (int nt = 0; nt < 16; nt++) {
            uint2 b = __ldg(bp + nt * 32);
            asm volatile(
                "mma.sync.aligned.m16n8k8.row.col.f32.tf32.tf32.f32 "
                "{%0,%1,%2,%3}, {%4,%5,%6,%7}, {%8,%9}, {%0,%1,%2,%3};"
                : "+f"(acc[nt][0]), "+f"(acc[nt][1]),
                  "+f"(acc[nt][2]), "+f"(acc[nt][3])
                : "r"(a0), "r"(a1), "r"(a2), "r"(a3), "r"(b.x), "r"(b.y));
        }
    }

    // epilogue: out = (1-beta)*h + beta*acc + bias
    const int lr   = w * 16 + (lane >> 2);   // local row of c0/c1
    const int row0 = r0 + lr;
    const int col0 = (lane & 3) * 2;
    #pragma unroll
    for (int nt = 0; nt < 16; nt++) {
        int col = nt * 8 + col0;
        float b0 = __ldg(&bias[col]);
        float b1 = __ldg(&bias[col + 1]);
        if (row0 < n) {
            float2 o;
            o.x = ONE_MB * sh[lr][col]     + BETA * acc[nt][0] + b0;
            o.y = ONE_MB * sh[lr][col + 1] + BETA * acc[nt][1] + b1;
            *(float2*)&out[(size_t)row0 * D + col] = o;
        }
        if (row0 + 8 < n) {
            float2 o;
            o.x = ONE_MB * sh[lr + 8][col]     + BETA * acc[nt][2] + b0;
            o.y = ONE_MB * sh[lr + 8][col + 1] + BETA * acc[nt][3] + b1;
            *(float2*)&out[(size_t)(row0 + 8) * D + col] = o;
        }
    }
}

extern "C" void kernel_launch(void* const* d_in, const int* in_sizes, int n_in,
                              void* d_out, int out_size) {
    const float* feat  = (const float*)d_in[0];
    const float* feat0 = (const float*)d_in[1];
    const float* W     = (const float*)d_in[2];
    const float* bias  = (const float*)d_in[3];
    const int*   src   = (const int*)d_in[4];
    const int*   dst   = (const int*)d_in[5];
    float* out = (float*)d_out;

    int n  = in_sizes[0] / D;
    int ne = in_sizes[4];
    int nb = (n + SCAN_B - 1) / SCAN_B;      // 196 for n=50000

    deg_kernel<<<(ne + 255) / 256, 256>>>(dst, ne);
    scan_block_kernel<<<nb, SCAN_B>>>(n);
    scan_finish_kernel<<<nb, SCAN_B>>>(n, ne);
    wconv_kernel<<<32, 256>>>(W);            // independent; overlaps fine
    permute_kernel<<<(ne + 255) / 256, 256>>>(src, dst, ne, n);

    int agg_blocks = (n * 32 + 255) / 256;   // one warp per row
    agg_kernel<<<agg_blocks, 256>>>(feat, feat0, n);

    mma_kernel<<<(n + GROWS - 1) / GROWS, 128>>>(bias, out, n);
}